// round 14
// baseline (speedup 1.0000x reference)
#include <cuda_runtime.h>
#include <cuda_bf16.h>
#include <cstdint>

#define NN   100000
#define EE   1600000
#define INC  512
#define HIDC 256
#define OUTC 32
#define ALPHA 0.1f

// ---------------- scratch (device globals; no allocation allowed) ----------------
__device__ float g_h0[(size_t)NN * OUTC];
__device__ float g_hA[(size_t)NN * OUTC];
__device__ float g_hB[(size_t)NN * OUTC];
__device__ int   g_deg[NN];
__device__ float g_dinv[NN];
__device__ int   g_ptr[NN + 1];
__device__ int   g_fill[NN];
__device__ int   g_rows[EE];
__device__ float g_norms[EE];
// split (hi|lo along K) bf16 images
__device__ __nv_bfloat16 g_x2 [(size_t)NN * 2 * INC];
__device__ __nv_bfloat16 g_h12[(size_t)NN * 2 * HIDC];
__device__ __nv_bfloat16 g_xr2[(size_t)NN * 2 * HIDC];
__device__ __nv_bfloat16 g_w1s[HIDC * 2 * INC];
__device__ __nv_bfloat16 g_wrs[HIDC * 2 * HIDC];
__device__ __nv_bfloat16 g_w2s[OUTC * 2 * HIDC];

// ---------------- side stream for CSR overlap (created at static init) ----------------
static cudaStream_t g_sB = nullptr;
static cudaEvent_t  g_evFork = nullptr, g_evJoin = nullptr;
struct StreamInit {
    StreamInit() {
        cudaStreamCreateWithFlags(&g_sB, cudaStreamNonBlocking);
        cudaEventCreateWithFlags(&g_evFork, cudaEventDisableTiming);
        cudaEventCreateWithFlags(&g_evJoin, cudaEventDisableTiming);
    }
};
static StreamInit g_stream_init;

// ---------------- PTX helpers (all baseline, no arch-"a" features) ----------------
__device__ __forceinline__ uint32_t cvta_smem(const void* p) {
    uint32_t a;
    asm("{ .reg .u64 t; cvta.to.shared.u64 t, %1; cvt.u32.u64 %0, t; }" : "=r"(a) : "l"(p));
    return a;
}
#define CP_ASYNC16(dst, src, sz) \
    asm volatile("cp.async.cg.shared.global [%0], [%1], 16, %2;" :: "r"(dst), "l"(src), "r"(sz))
#define CP_COMMIT() asm volatile("cp.async.commit_group;")
#define CP_WAIT1()  asm volatile("cp.async.wait_group 1;")
#define LDSM4(R, addr) \
    asm volatile("ldmatrix.sync.aligned.m8n8.x4.shared.b16 {%0,%1,%2,%3}, [%4];" \
                 : "=r"((R)[0]), "=r"((R)[1]), "=r"((R)[2]), "=r"((R)[3]) : "r"(addr))

__device__ __forceinline__ void mma16816(float* c, const uint32_t* a, uint32_t b0, uint32_t b1)
{
    asm volatile(
        "mma.sync.aligned.m16n8k16.row.col.f32.bf16.bf16.f32 "
        "{%0,%1,%2,%3}, {%4,%5,%6,%7}, {%8,%9}, {%0,%1,%2,%3};"
        : "+f"(c[0]), "+f"(c[1]), "+f"(c[2]), "+f"(c[3])
        : "r"(a[0]), "r"(a[1]), "r"(a[2]), "r"(a[3]), "r"(b0), "r"(b1));
}
__device__ __forceinline__ uint32_t pack_bf16(float a, float b)
{
    __nv_bfloat16 ha = __float2bfloat16(a), hb = __float2bfloat16(b);
    unsigned short ua = *reinterpret_cast<unsigned short*>(&ha);
    unsigned short ub = *reinterpret_cast<unsigned short*>(&hb);
    return (uint32_t)ua | ((uint32_t)ub << 16);
}

// ---------------- split: X[M,K] fp32 -> X2[M,2K] bf16 ([hi | lo] along K) ----------------
__global__ void split_act(const float* __restrict__ X, __nv_bfloat16* __restrict__ X2,
                          int M, int K)
{
    int idx = blockIdx.x * blockDim.x + threadIdx.x;
    int tot = M * (K / 4);
    if (idx >= tot) return;
    int r = idx / (K / 4);
    int c = (idx % (K / 4)) * 4;
    float4 v = *reinterpret_cast<const float4*>(&X[(size_t)r * K + c]);
    __nv_bfloat16 h0 = __float2bfloat16(v.x), h1 = __float2bfloat16(v.y),
                  h2 = __float2bfloat16(v.z), h3 = __float2bfloat16(v.w);
    float l0 = v.x - __bfloat162float(h0), l1 = v.y - __bfloat162float(h1);
    float l2 = v.z - __bfloat162float(h2), l3 = v.w - __bfloat162float(h3);
    size_t base = (size_t)r * 2 * K;
    unsigned short uh0 = *reinterpret_cast<unsigned short*>(&h0);
    unsigned short uh1 = *reinterpret_cast<unsigned short*>(&h1);
    unsigned short uh2 = *reinterpret_cast<unsigned short*>(&h2);
    unsigned short uh3 = *reinterpret_cast<unsigned short*>(&h3);
    *reinterpret_cast<uint2*>(&X2[base + c]) =
        make_uint2((uint32_t)uh0 | ((uint32_t)uh1 << 16), (uint32_t)uh2 | ((uint32_t)uh3 << 16));
    *reinterpret_cast<uint2*>(&X2[base + K + c]) =
        make_uint2(pack_bf16(l0, l1), pack_bf16(l2, l3));
}

// ---------------- 512-thread bf16 GEMM, 3-phase compensated split, full-N CTA --------
// 16 warps in a 4x4 grid; warp tile 32x64 (64 acc regs — the no-spill shape).
// A2/W2 are [M,2K] bf16 ([hi | lo] along K). Stages: hi*hi, lo*hi, hi*lo.
// MODE 1: relu, write C2 split               (layer 1)
// MODE 2: relu + resid(hi+lo), write C2      (layer 2)
template<int K, int MODE>
__global__ void __launch_bounds__(512)
gemm_bf16_512(const __nv_bfloat16* __restrict__ A2, const __nv_bfloat16* __restrict__ W2,
              const float* __restrict__ bias, __nv_bfloat16* __restrict__ C2,
              const __nv_bfloat16* __restrict__ resid2, int M, int N)
{
    constexpr int BM = 128, BN = 256, BK = 64;
    constexpr int K2 = 2 * K;
    constexpr int TPK = K / BK;
    constexpr int NS = 3 * TPK;
    constexpr int SROW = 72;                 // padded smem row stride (bf16) = 144B
    constexpr int ABYTES = BM * SROW * 2;    // 18432
    constexpr int BBYTES = BN * SROW * 2;    // 36864

    extern __shared__ __align__(16) char dsm[];
    const uint32_t s0 = cvta_smem(dsm);

    const int tid  = threadIdx.x;
    const int wid  = tid >> 5;
    const int lane = tid & 31;
    const int grp  = lane >> 2;
    const int qp   = lane & 3;
    const int wm   = wid >> 2;               // 0..3
    const int wn   = wid & 3;                // 0..3
    const int bm   = blockIdx.x * BM;

    const int lrow = lane & 15;
    const int lkh  = lane >> 4;
    const uint32_t aoff = (uint32_t)(wm * 32 + lrow) * (SROW * 2) + lkh * 16;
    const uint32_t boff = (uint32_t)(wn * 64 + lrow) * (SROW * 2) + lkh * 16;

    float acc[2][8][4];                      // 2 m16 x 8 n8 x 4 = 64 regs
#pragma unroll
    for (int mt = 0; mt < 2; mt++)
#pragma unroll
        for (int nt = 0; nt < 8; nt++)
#pragma unroll
            for (int j = 0; j < 4; j++) acc[mt][nt][j] = 0.0f;

    auto fill = [&](int buf, int stage) {
        int phase = stage / TPK;
        int t     = stage % TPK;
        int kA = ((phase == 1) ? K : 0) + t * BK;
        int kW = ((phase == 2) ? K : 0) + t * BK;
        uint32_t sa = s0 + buf * ABYTES;
        uint32_t sb = s0 + 2 * ABYTES + buf * BBYTES;
        // A: 128 rows x 8 chunks of 16B = 1024 ops / 512 threads
#pragma unroll
        for (int i = 0; i < 2; i++) {
            int idx = tid + i * 512;
            int row = idx >> 3, c = idx & 7;
            const __nv_bfloat16* src = A2 + (size_t)(bm + row) * K2 + kA + c * 8;
            uint32_t sz = (bm + row < M) ? 16u : 0u;
            CP_ASYNC16(sa + row * (SROW * 2) + c * 16, src, sz);
        }
        // B: 256 rows x 8 chunks = 2048 ops / 512 threads
#pragma unroll
        for (int i = 0; i < 4; i++) {
            int idx = tid + i * 512;
            int row = idx >> 3, c = idx & 7;
            const __nv_bfloat16* src = W2 + (size_t)row * K2 + kW + c * 8;
            CP_ASYNC16(sb + row * (SROW * 2) + c * 16, src, 16u);
        }
    };

    fill(0, 0);
    CP_COMMIT();

    for (int s = 0; s < NS; s++) {
        if (s + 1 < NS) fill((s + 1) & 1, s + 1);
        CP_COMMIT();
        CP_WAIT1();
        __syncthreads();

        uint32_t abase = s0 + (s & 1) * ABYTES + aoff;
        uint32_t bbase = s0 + 2 * ABYTES + (s & 1) * BBYTES + boff;
#pragma unroll
        for (int ks = 0; ks < BK / 16; ks++) {
            uint32_t a0[4], a1[4];
            LDSM4(a0, abase + ks * 32);
            LDSM4(a1, abase + 16 * (SROW * 2) + ks * 32);
#pragma unroll
            for (int t = 0; t < 4; t++) {    // 4 n16 groups per warp
                uint32_t bb[4];
                LDSM4(bb, bbase + t * 16 * (SROW * 2) + ks * 32);
                mma16816(acc[0][2 * t],     a0, bb[0], bb[2]);
                mma16816(acc[0][2 * t + 1], a0, bb[1], bb[3]);
                mma16816(acc[1][2 * t],     a1, bb[0], bb[2]);
                mma16816(acc[1][2 * t + 1], a1, bb[1], bb[3]);
            }
        }
        __syncthreads();
    }

    // ---- epilogue: bias / relu / optional residual, write split bf16 [hi|lo] ----
#pragma unroll
    for (int mt = 0; mt < 2; mt++) {
        int row0 = bm + wm * 32 + mt * 16 + grp;
        int row1 = row0 + 8;
#pragma unroll
        for (int t = 0; t < 4; t++) {
#pragma unroll
            for (int h = 0; h < 2; h++) {
                int nt = 2 * t + h;
                int col = wn * 64 + t * 16 + h * 8 + qp * 2;
                float bx = bias[col], by = bias[col + 1];
                float o0 = acc[mt][nt][0] + bx, o1 = acc[mt][nt][1] + by;
                float o2 = acc[mt][nt][2] + bx, o3 = acc[mt][nt][3] + by;
                o0 = fmaxf(o0, 0.f); o1 = fmaxf(o1, 0.f);
                o2 = fmaxf(o2, 0.f); o3 = fmaxf(o3, 0.f);
                if (MODE == 2) {  // residual = hi + lo of split image
                    if (row0 < M) {
                        size_t b0 = (size_t)row0 * 2 * N;
                        __nv_bfloat162 vh = *reinterpret_cast<const __nv_bfloat162*>(&resid2[b0 + col]);
                        __nv_bfloat162 vl = *reinterpret_cast<const __nv_bfloat162*>(&resid2[b0 + N + col]);
                        o0 += __bfloat162float(vh.x) + __bfloat162float(vl.x);
                        o1 += __bfloat162float(vh.y) + __bfloat162float(vl.y);
                    }
                    if (row1 < M) {
                        size_t b1 = (size_t)row1 * 2 * N;
                        __nv_bfloat162 vh = *reinterpret_cast<const __nv_bfloat162*>(&resid2[b1 + col]);
                        __nv_bfloat162 vl = *reinterpret_cast<const __nv_bfloat162*>(&resid2[b1 + N + col]);
                        o2 += __bfloat162float(vh.x) + __bfloat162float(vl.x);
                        o3 += __bfloat162float(vh.y) + __bfloat162float(vl.y);
                    }
                }
                if (row0 < M) {
                    size_t b0 = (size_t)row0 * 2 * N;
                    __nv_bfloat16 hh0 = __float2bfloat16(o0), hh1 = __float2bfloat16(o1);
                    unsigned short u0 = *reinterpret_cast<unsigned short*>(&hh0);
                    unsigned short u1 = *reinterpret_cast<unsigned short*>(&hh1);
                    *reinterpret_cast<uint32_t*>(&C2[b0 + col]) = (uint32_t)u0 | ((uint32_t)u1 << 16);
                    *reinterpret_cast<uint32_t*>(&C2[b0 + N + col]) =
                        pack_bf16(o0 - __bfloat162float(hh0), o1 - __bfloat162float(hh1));
                }
                if (row1 < M) {
                    size_t b1 = (size_t)row1 * 2 * N;
                    __nv_bfloat16 hh2 = __float2bfloat16(o2), hh3 = __float2bfloat16(o3);
                    unsigned short u2 = *reinterpret_cast<unsigned short*>(&hh2);
                    unsigned short u3 = *reinterpret_cast<unsigned short*>(&hh3);
                    *reinterpret_cast<uint32_t*>(&C2[b1 + col]) = (uint32_t)u2 | ((uint32_t)u3 << 16);
                    *reinterpret_cast<uint32_t*>(&C2[b1 + N + col]) =
                        pack_bf16(o2 - __bfloat162float(hh2), o3 - __bfloat162float(hh3));
                }
            }
        }
    }
}

// ---------------- 256-thread GEMM for layer 3 (BN=32, fp32 out) ----------------------
template<int BN, int K>
__global__ void __launch_bounds__(256)
gemm_bf16_s(const __nv_bfloat16* __restrict__ A2, const __nv_bfloat16* __restrict__ W2,
            const float* __restrict__ bias, float* __restrict__ Cf, int M, int N)
{
    constexpr int BM = 128, BK = 64;
    constexpr int K2 = 2 * K;
    constexpr int TPK = K / BK;
    constexpr int NS = 3 * TPK;
    constexpr int SROW = 72;
    constexpr int ABYTES = BM * SROW * 2;
    constexpr int BBYTES = BN * SROW * 2;
    constexpr int NGRP = BN / 32;

    extern __shared__ __align__(16) char dsm[];
    const uint32_t s0 = cvta_smem(dsm);

    const int tid  = threadIdx.x;
    const int wid  = tid >> 5;
    const int lane = tid & 31;
    const int grp  = lane >> 2;
    const int qp   = lane & 3;
    const int wm   = wid >> 1;
    const int wn   = wid & 1;
    const int bm   = blockIdx.x * BM;

    const int lrow = lane & 15;
    const int lkh  = lane >> 4;
    const uint32_t aoff = (uint32_t)(wm * 32 + lrow) * (SROW * 2) + lkh * 16;
    const uint32_t boff = (uint32_t)(wn * (BN / 2) + lrow) * (SROW * 2) + lkh * 16;

    float acc[2][BN / 16][4];
#pragma unroll
    for (int mt = 0; mt < 2; mt++)
#pragma unroll
        for (int nt = 0; nt < BN / 16; nt++)
#pragma unroll
            for (int j = 0; j < 4; j++) acc[mt][nt][j] = 0.0f;

    auto fill = [&](int buf, int stage) {
        int phase = stage / TPK;
        int t     = stage % TPK;
        int kA = ((phase == 1) ? K : 0) + t * BK;
        int kW = ((phase == 2) ? K : 0) + t * BK;
        uint32_t sa = s0 + buf * ABYTES;
        uint32_t sb = s0 + 2 * ABYTES + buf * BBYTES;
#pragma unroll
        for (int i = 0; i < 4; i++) {
            int idx = tid + i * 256;
            int row = idx >> 3, c = idx & 7;
            const __nv_bfloat16* src = A2 + (size_t)(bm + row) * K2 + kA + c * 8;
            uint32_t sz = (bm + row < M) ? 16u : 0u;
            CP_ASYNC16(sa + row * (SROW * 2) + c * 16, src, sz);
        }
#pragma unroll
        for (int i = 0; i < (BN * 8) / 256; i++) {
            int idx = tid + i * 256;
            int row = idx >> 3, c = idx & 7;
            const __nv_bfloat16* src = W2 + (size_t)row * K2 + kW + c * 8;
            CP_ASYNC16(sb + row * (SROW * 2) + c * 16, src, 16u);
        }
    };

    fill(0, 0);
    CP_COMMIT();

    for (int s = 0; s < NS; s++) {
        if (s + 1 < NS) fill((s + 1) & 1, s + 1);
        CP_COMMIT();
        CP_WAIT1();
        __syncthreads();

        uint32_t abase = s0 + (s & 1) * ABYTES + aoff;
        uint32_t bbase = s0 + 2 * ABYTES + (s & 1) * BBYTES + boff;
#pragma unroll
        for (int ks = 0; ks < BK / 16; ks++) {
            uint32_t a0[4], a1[4];
            LDSM4(a0, abase + ks * 32);
            LDSM4(a1, abase + 16 * (SROW * 2) + ks * 32);
#pragma unroll
            for (int t = 0; t < NGRP; t++) {
                uint32_t bb[4];
                LDSM4(bb, bbase + t * 16 * (SROW * 2) + ks * 32);
                mma16816(acc[0][2 * t],     a0, bb[0], bb[2]);
                mma16816(acc[0][2 * t + 1], a0, bb[1], bb[3]);
                mma16816(acc[1][2 * t],     a1, bb[0], bb[2]);
                mma16816(acc[1][2 * t + 1], a1, bb[1], bb[3]);
            }
        }
        __syncthreads();
    }

#pragma unroll
    for (int mt = 0; mt < 2; mt++) {
        int row0 = bm + wm * 32 + mt * 16 + grp;
        int row1 = row0 + 8;
#pragma unroll
        for (int t = 0; t < NGRP; t++) {
#pragma unroll
            for (int h = 0; h < 2; h++) {
                int nt = 2 * t + h;
                int col = wn * (BN / 2) + t * 16 + h * 8 + qp * 2;
                float bx = bias[col], by = bias[col + 1];
                float o0 = acc[mt][nt][0] + bx, o1 = acc[mt][nt][1] + by;
                float o2 = acc[mt][nt][2] + bx, o3 = acc[mt][nt][3] + by;
                if (row0 < M)
                    *reinterpret_cast<float2*>(&Cf[(size_t)row0 * N + col]) = make_float2(o0, o1);
                if (row1 < M)
                    *reinterpret_cast<float2*>(&Cf[(size_t)row1 * N + col]) = make_float2(o2, o3);
            }
        }
    }
}

// ---------------- graph preprocessing (edge_index is int32) ----------------
__global__ void init_kernel(int* __restrict__ deg, int* __restrict__ fill)
{
    int v = blockIdx.x * blockDim.x + threadIdx.x;
    if (v < NN) { deg[v] = 1; fill[v] = 0; }
}

__global__ void count_kernel(const int* __restrict__ ei, int* __restrict__ deg)
{
    int e = blockIdx.x * blockDim.x + threadIdx.x;
    if (e < EE) {
        int c = ei[EE + e];
        if (c >= 0 && c < NN) atomicAdd(&deg[c], 1);
    }
}

__global__ void dinv_kernel(const int* __restrict__ deg, float* __restrict__ dinv)
{
    int v = blockIdx.x * blockDim.x + threadIdx.x;
    if (v < NN) dinv[v] = rsqrtf((float)deg[v]);
}

__global__ void __launch_bounds__(1024) scan_kernel(const int* __restrict__ deg, int* __restrict__ ptr)
{
    __shared__ int warpsums[32];
    __shared__ int s_carry;
    const int tid = threadIdx.x;
    const int lane = tid & 31;
    const int wid = tid >> 5;
    if (tid == 0) s_carry = 0;
    __syncthreads();

    for (int start = 0; start < NN; start += 1024) {
        int idx = start + tid;
        int v = (idx < NN) ? (deg[idx] - 1) : 0;
        int incl = v;
#pragma unroll
        for (int o = 1; o < 32; o <<= 1) {
            int t = __shfl_up_sync(0xFFFFFFFFu, incl, o);
            if (lane >= o) incl += t;
        }
        if (lane == 31) warpsums[wid] = incl;
        __syncthreads();
        if (wid == 0) {
            int w = warpsums[lane];
            int wi = w;
#pragma unroll
            for (int o = 1; o < 32; o <<= 1) {
                int t = __shfl_up_sync(0xFFFFFFFFu, wi, o);
                if (lane >= o) wi += t;
            }
            warpsums[lane] = wi - w;
        }
        __syncthreads();
        int excl = s_carry + warpsums[wid] + incl - v;
        if (idx < NN) ptr[idx] = excl;
        __syncthreads();
        if (tid == 1023) s_carry += warpsums[31] + incl;
        __syncthreads();
    }
    if (threadIdx.x == 0) ptr[NN] = s_carry;
}

__global__ void fill_kernel(const int* __restrict__ ei,
                            const int* __restrict__ ptr, int* __restrict__ fill,
                            const float* __restrict__ dinv,
                            int* __restrict__ rows, float* __restrict__ norms)
{
    int e = blockIdx.x * blockDim.x + threadIdx.x;
    if (e < EE) {
        int r = ei[e];
        int c = ei[EE + e];
        if (c < 0 || c >= NN) return;
        int pos = ptr[c] + atomicAdd(&fill[c], 1);
        bool rok = (r >= 0 && r < NN);
        int rr = rok ? r : 0;
        rows[pos]  = rr;
        norms[pos] = rok ? dinv[rr] * dinv[c] : 0.0f;
    }
}

// ---------------- APPNP propagation: one warp per node, lane = channel ----------------
__global__ void __launch_bounds__(256)
prop_kernel(const float* __restrict__ src, const float* __restrict__ h0,
            float* __restrict__ dst,
            const int* __restrict__ ptr, const int* __restrict__ rows,
            const float* __restrict__ norms, const float* __restrict__ dinv)
{
    int gw = (blockIdx.x * blockDim.x + threadIdx.x) >> 5;
    int lane = threadIdx.x & 31;
    if (gw >= NN) return;

    int beg = ptr[gw];
    int end = ptr[gw + 1];

    float acc = 0.0f;
    int i = beg;
    for (; i + 4 <= end; i += 4) {
        int   r0 = rows[i + 0], r1 = rows[i + 1], r2 = rows[i + 2], r3 = rows[i + 3];
        float w0 = norms[i + 0], w1 = norms[i + 1], w2 = norms[i + 2], w3 = norms[i + 3];
        float v0 = src[(size_t)r0 * OUTC + lane];
        float v1 = src[(size_t)r1 * OUTC + lane];
        float v2 = src[(size_t)r2 * OUTC + lane];
        float v3 = src[(size_t)r3 * OUTC + lane];
        acc = fmaf(w0, v0, acc);
        acc = fmaf(w1, v1, acc);
        acc = fmaf(w2, v2, acc);
        acc = fmaf(w3, v3, acc);
    }
    for (; i < end; ++i)
        acc = fmaf(norms[i], src[(size_t)rows[i] * OUTC + lane], acc);

    float dv = dinv[gw];
    acc = fmaf(dv * dv, src[(size_t)gw * OUTC + lane], acc);

    dst[(size_t)gw * OUTC + lane] =
        fmaf(1.0f - ALPHA, acc, ALPHA * h0[(size_t)gw * OUTC + lane]);
}

// ---------------- launch ----------------
extern "C" void kernel_launch(void* const* d_in, const int* in_sizes, int n_in,
                              void* d_out, int out_size)
{
    const float* x = nullptr; const int* ei = nullptr;
    const float *W1 = nullptr, *b1 = nullptr, *Wr = nullptr, *br = nullptr,
                *W2 = nullptr, *b2 = nullptr;
    for (int i = 0; i < n_in; i++) {
        switch (in_sizes[i]) {
            case 51200000: x  = (const float*)d_in[i]; break;
            case  3200000: ei = (const int*)d_in[i]; break;
            case   131072: W1 = (const float*)d_in[i]; break;
            case    65536: Wr = (const float*)d_in[i]; break;
            case     8192: W2 = (const float*)d_in[i]; break;
            case       32: b2 = (const float*)d_in[i]; break;
            case      256: if (!b1) b1 = (const float*)d_in[i];
                           else     br = (const float*)d_in[i]; break;
            default: break;
        }
    }
    if (!x || !ei || !W1 || !b1 || !Wr || !br || !W2 || !b2) {
        x  = (const float*)d_in[0];     ei = (const int*)d_in[1];
        W1 = (const float*)d_in[2];     b1 = (const float*)d_in[3];
        Wr = (const float*)d_in[4];     br = (const float*)d_in[5];
        W2 = (const float*)d_in[6];     b2 = (const float*)d_in[7];
    }
    float* out = (float*)d_out;

    float *h0, *hA, *hB, *dinv, *norms;
    int *deg, *ptr, *fil, *rows;
    __nv_bfloat16 *x2, *h12, *xr2, *w1s, *wrs, *w2s;
    cudaGetSymbolAddress((void**)&h0,    g_h0);
    cudaGetSymbolAddress((void**)&hA,    g_hA);
    cudaGetSymbolAddress((void**)&hB,    g_hB);
    cudaGetSymbolAddress((void**)&dinv,  g_dinv);
    cudaGetSymbolAddress((void**)&norms, g_norms);
    cudaGetSymbolAddress((void**)&deg,   g_deg);
    cudaGetSymbolAddress((void**)&ptr,   g_ptr);
    cudaGetSymbolAddress((void**)&fil,   g_fill);
    cudaGetSymbolAddress((void**)&rows,  g_rows);
    cudaGetSymbolAddress((void**)&x2,    g_x2);
    cudaGetSymbolAddress((void**)&h12,   g_h12);
    cudaGetSymbolAddress((void**)&xr2,   g_xr2);
    cudaGetSymbolAddress((void**)&w1s,   g_w1s);
    cudaGetSymbolAddress((void**)&wrs,   g_wrs);
    cudaGetSymbolAddress((void**)&w2s,   g_w2s);

    // dynamic smem
    const int smem_512 = 2 * 18432 + 2 * 256 * 144;  // 110592 (A + full-N B, double buffered)
    const int smem_32  = 2 * 18432 + 2 * 32 * 144;   //  46080
    cudaFuncSetAttribute(gemm_bf16_512<INC,  1>, cudaFuncAttributeMaxDynamicSharedMemorySize, smem_512);
    cudaFuncSetAttribute(gemm_bf16_512<HIDC, 2>, cudaFuncAttributeMaxDynamicSharedMemorySize, smem_512);
    cudaFuncSetAttribute(gemm_bf16_s<32, HIDC>,  cudaFuncAttributeMaxDynamicSharedMemorySize, smem_32);

    // ---- fork: CSR build runs on side stream, concurrent with splits+GEMMs ----
    cudaEventRecord(g_evFork, 0);
    cudaStreamWaitEvent(g_sB, g_evFork, 0);
    init_kernel <<<(NN + 255) / 256, 256, 0, g_sB>>>(deg, fil);
    count_kernel<<<(EE + 255) / 256, 256, 0, g_sB>>>(ei, deg);
    dinv_kernel <<<(NN + 255) / 256, 256, 0, g_sB>>>(deg, dinv);
    scan_kernel <<<1, 1024, 0, g_sB>>>(deg, ptr);
    fill_kernel <<<(EE + 255) / 256, 256, 0, g_sB>>>(ei, ptr, fil, dinv, rows, norms);
    cudaEventRecord(g_evJoin, g_sB);

    // ---- splits (x + weights) on main stream ----
    split_act<<<(NN * (INC / 4) + 255) / 256, 256>>>(x, x2, NN, INC);
    split_act<<<(HIDC * (INC / 4) + 255) / 256, 256>>>(W1, w1s, HIDC, INC);
    split_act<<<(HIDC * (HIDC / 4) + 255) / 256, 256>>>(Wr, wrs, HIDC, HIDC);
    split_act<<<(OUTC * (HIDC / 4) + 255) / 256, 256>>>(W2, w2s, OUTC, HIDC);

    // ---- MLP (bf16 3-phase compensated tensor-core GEMMs, full-N 512-thread CTAs) ----
    const int ntiles = (NN + 127) / 128;
    gemm_bf16_512<INC,  1><<<ntiles, 512, smem_512>>>(x2,  w1s, b1, h12, nullptr, NN, HIDC);
    gemm_bf16_512<HIDC, 2><<<ntiles, 512, smem_512>>>(h12, wrs, br, xr2, h12,     NN, HIDC);
    gemm_bf16_s<32, HIDC><<<ntiles, 256, smem_32>>>(xr2, w2s, b2, h0, NN, OUTC);

    // ---- join: CSR must be done before propagation ----
    cudaStreamWaitEvent(0, g_evJoin, 0);

    // ---- K = 10 propagation steps ----
    const int nblk = (NN * 32 + 255) / 256;
    prop_kernel<<<nblk, 256>>>(h0, h0, hA, ptr, rows, norms, dinv);
    prop_kernel<<<nblk, 256>>>(hA, h0, hB, ptr, rows, norms, dinv);
    prop_kernel<<<nblk, 256>>>(hB, h0, hA, ptr, rows, norms, dinv);
    prop_kernel<<<nblk, 256>>>(hA, h0, hB, ptr, rows, norms, dinv);
    prop_kernel<<<nblk, 256>>>(hB, h0, hA, ptr, rows, norms, dinv);
    prop_kernel<<<nblk, 256>>>(hA, h0, hB, ptr, rows, norms, dinv);
    prop_kernel<<<nblk, 256>>>(hB, h0, hA, ptr, rows, norms, dinv);
    prop_kernel<<<nblk, 256>>>(hA, h0, hB, ptr, rows, norms, dinv);
    prop_kernel<<<nblk, 256>>>(hB, h0, hA, ptr, rows, norms, dinv);
    prop_kernel<<<nblk, 256>>>(hA, h0, out, ptr, rows, norms, dinv);
}